// round 7
// baseline (speedup 1.0000x reference)
#include <cuda_runtime.h>

#define BB   32
#define DIMC 512
#define CC   128
#define WSZ  14
#define NN   196
#define NHD  4
#define HD   32
#define HIN  56

// Scratch (device globals; no runtime allocation)
__device__ float g_q[BB * NHD * NN * HD];  // [B][H][N][D] (pre-scaled via wT)
__device__ float g_k[BB * NHD * NN * HD];
__device__ float g_v[BB * NHD * NN * HD];
__device__ float g_ot[BB * CC * NN];       // attention output TRANSPOSED [B][C][N]
__device__ float g_wf[DIMC * CC];          // fused convout@proj weight [512][128]
__device__ float g_bf[DIMC];               // fused bias
__device__ float g_wqkvT[CC * 3 * CC];     // qkv weight transposed [c][j], q rows pre-scaled

// ---------------------------------------------------------------------------
// K0: prep. blocks 0..511: Wf = convout_w @ proj_w, bf = convout_w@proj_b + cb
//          blocks 512..639: transpose qkv_w -> [c][j], q rows pre-scaled
// grid 640, block 384
// ---------------------------------------------------------------------------
__global__ void prep_kernel(const float* __restrict__ cw,
                            const float* __restrict__ cb,
                            const float* __restrict__ pw,
                            const float* __restrict__ pb,
                            const float* __restrict__ qkvw)
{
    int t = threadIdx.x;
    if (blockIdx.x < DIMC) {
        int oc = blockIdx.x;
        __shared__ float row[CC];
        __shared__ float red[CC];
        if (t < CC) row[t] = cw[oc * CC + t];
        __syncthreads();
        if (t < CC) {
            float acc = 0.0f;
            for (int k = 0; k < CC; k++) acc += row[k] * pw[k * CC + t];
            g_wf[oc * CC + t] = acc;
            red[t] = row[t] * pb[t];
        }
        __syncthreads();
        for (int s = 64; s > 0; s >>= 1) {
            if (t < s) red[t] += red[t + s];
            __syncthreads();
        }
        if (t == 0) g_bf[oc] = red[0] + cb[oc];
    } else {
        int c = blockIdx.x - DIMC;      // 0..127
        float v = qkvw[t * CC + c];
        if (t < CC) v *= 0.17677669529663687f;
        g_wqkvT[c * 384 + t] = v;
    }
}

// ---------------------------------------------------------------------------
// K1: FUSED grouped conv 4x4 s4 + BN + ReLU6 + qkv GEMM.
// grid (7 token-tiles, B), block 448.
// ---------------------------------------------------------------------------
#define TS_STRIDE 132

__global__ void __launch_bounds__(448, 2)
convqkv_kernel(const float* __restrict__ x,
               const float* __restrict__ cw,
               const float* __restrict__ cb,
               const float* __restrict__ gamma,
               const float* __restrict__ beta,
               const float* __restrict__ mean,
               const float* __restrict__ var)
{
    __shared__ float ws[CC * 64];          // 32KB conv weights
    __shared__ float bnsc[CC], bnsh[CC];
    __shared__ float ts[28 * TS_STRIDE];   // token tile, padded

    int tile = blockIdx.x, b = blockIdx.y;
    int t = threadIdx.x;

    for (int idx = t; idx < CC * 64 / 4; idx += 448)
        ((float4*)ws)[idx] = ((const float4*)cw)[idx];
    if (t < CC) {
        float sc = gamma[t] * rsqrtf(var[t] + 1e-5f);
        bnsc[t] = sc;
        bnsh[t] = cb[t] * sc + beta[t] - mean[t] * sc;
    }
    __syncthreads();

    // ---- Phase 1: conv ----
    {
        int n = t % 28, cl = t / 28;       // cl 0..15
        int oh = tile * 2 + n / WSZ, ow = n % WSZ;
        const float* xb = x + (size_t)b * DIMC * HIN * HIN + (4 * oh) * HIN + 4 * ow;
#pragma unroll
        for (int p = 0; p < 8; p++) {
            int c = p * 16 + cl;
            float acc = 0.0f;
            const float* wp0 = ws + c * 64;
            const float* xc = xb + (size_t)(4 * c) * HIN * HIN;
#pragma unroll
            for (int i = 0; i < 4; i++) {
                const float* xp = xc + (size_t)i * HIN * HIN;
#pragma unroll
                for (int kh = 0; kh < 4; kh++) {
                    float4 v = *(const float4*)(xp + kh * HIN);
                    const float* wp = wp0 + i * 16 + kh * 4;
                    acc += v.x * wp[0] + v.y * wp[1] + v.z * wp[2] + v.w * wp[3];
                }
            }
            acc = acc * bnsc[c] + bnsh[c];
            ts[n * TS_STRIDE + c] = fminf(fmaxf(acc, 0.0f), 6.0f);
        }
    }
    __syncthreads();

    // ---- Phase 2: qkv GEMM (threads 0..383) ----
    if (t < 384) {
        int jp = (t % 192) * 2;
        int rg = t / 192;
        int n0 = tile * 28;

        float acc0[14], acc1[14];
#pragma unroll
        for (int r = 0; r < 14; r++) { acc0[r] = 0.0f; acc1[r] = 0.0f; }

        const float* tsb = ts + (rg * 14) * TS_STRIDE;
        for (int cq = 0; cq < 32; cq++) {
            int c = cq * 4;
            float2 w0 = *(const float2*)(g_wqkvT + (size_t)(c + 0) * 384 + jp);
            float2 w1 = *(const float2*)(g_wqkvT + (size_t)(c + 1) * 384 + jp);
            float2 w2 = *(const float2*)(g_wqkvT + (size_t)(c + 2) * 384 + jp);
            float2 w3 = *(const float2*)(g_wqkvT + (size_t)(c + 3) * 384 + jp);
#pragma unroll
            for (int r = 0; r < 14; r++) {
                float4 tv = *(const float4*)(tsb + r * TS_STRIDE + c);
                acc0[r] += tv.x * w0.x + tv.y * w1.x + tv.z * w2.x + tv.w * w3.x;
                acc1[r] += tv.x * w0.y + tv.y * w1.y + tv.z * w2.y + tv.w * w3.y;
            }
        }

#pragma unroll
        for (int which = 0; which < 2; which++) {
            int j = jp + which;
            int s = j / CC, rem = j % CC;
            int h = rem / HD, d = rem % HD;
            float* dst = (s == 0) ? g_q : ((s == 1) ? g_k : g_v);
            dst += (((size_t)(b * NHD + h)) * NN + n0 + rg * 14) * HD + d;
            const float* a = which ? acc1 : acc0;
#pragma unroll
            for (int r = 0; r < 14; r++) dst[r * HD] = a[r];
        }
    }
}

// ---------------------------------------------------------------------------
// K2: attention. grid (4 q-tiles, 128 bh), block 224.
// ---------------------------------------------------------------------------
#define KV_STRIDE 36
#define ATTN_SMEM ((196 * KV_STRIDE * 2 + 729) * 4)

__global__ void attn_kernel(const float* __restrict__ rpb)
{
    extern __shared__ float sm[];
    float* ks_s  = sm;
    float* vs_s  = sm + 196 * KV_STRIDE;
    float* rpb_s = sm + 196 * KV_STRIDE * 2;

    int qt = blockIdx.x;
    int bh = blockIdx.y;
    int h  = bh & 3;
    int t  = threadIdx.x;
    int qi = t >> 2, ks = t & 3;
    bool active = (qi < 49);
    int q = active ? (qt * 49 + qi) : 195;

    const float* kb = g_k + (size_t)bh * NN * HD;
    const float* vb = g_v + (size_t)bh * NN * HD;
    for (int idx = t; idx < 196 * 8; idx += 224) {
        int r = idx >> 3, qd = idx & 7;
        *(float4*)(ks_s + r * KV_STRIDE + qd * 4) = ((const float4*)(kb + r * HD))[qd];
        *(float4*)(vs_s + r * KV_STRIDE + qd * 4) = ((const float4*)(vb + r * HD))[qd];
    }
    for (int i = t; i < 729; i += 224) rpb_s[i] = rpb[i * NHD + h];
    __syncthreads();

    float4 q4[8];
    const float4* qp = (const float4*)(g_q + ((size_t)bh * NN + q) * HD);
#pragma unroll
    for (int i = 0; i < 8; i++) q4[i] = qp[i];
    int r1 = q / WSZ, c1 = q % WSZ;

    float mx = -1e30f, sum = 0.0f;
    float acc[32];
#pragma unroll
    for (int d = 0; d < 32; d++) acc[d] = 0.0f;

    int base_m = ks * 49;
    for (int g = 0; g < 7; g++) {
        int m0 = base_m + g * 7;
        float s[7];
#pragma unroll
        for (int u = 0; u < 7; u++) {
            const float* kr = ks_s + (m0 + u) * KV_STRIDE;
            float sv = 0.0f;
#pragma unroll
            for (int qd = 0; qd < 8; qd++) {
                float4 kv = *(const float4*)(kr + qd * 4);
                sv += q4[qd].x * kv.x + q4[qd].y * kv.y + q4[qd].z * kv.z + q4[qd].w * kv.w;
            }
            int m = m0 + u;
            int r2 = m / WSZ, c2 = m % WSZ;
            s[u] = sv + rpb_s[(r1 - r2 + 13) * 27 + (c1 - c2 + 13)];
        }
        float gm = s[0];
#pragma unroll
        for (int u = 1; u < 7; u++) gm = fmaxf(gm, s[u]);
        float nm = fmaxf(mx, gm);
        float corr = __expf(mx - nm);
        mx = nm;
        float ps = 0.0f;
#pragma unroll
        for (int u = 0; u < 7; u++) { s[u] = __expf(s[u] - nm); ps += s[u]; }
        sum = sum * corr + ps;

#pragma unroll
        for (int qd = 0; qd < 8; qd++) {
            float4 vv[7];
#pragma unroll
            for (int u = 0; u < 7; u++)
                vv[u] = *(const float4*)(vs_s + (m0 + u) * KV_STRIDE + qd * 4);
#pragma unroll
            for (int z = 0; z < 4; z++) {
                float a = acc[qd * 4 + z] * corr;
#pragma unroll
                for (int u = 0; u < 7; u++)
                    a += s[u] * ((const float*)&vv[u])[z];
                acc[qd * 4 + z] = a;
            }
        }
    }

#pragma unroll
    for (int off = 1; off <= 2; off <<= 1) {
        float m2 = __shfl_xor_sync(0xffffffffu, mx, off);
        float s2 = __shfl_xor_sync(0xffffffffu, sum, off);
        float nm = fmaxf(mx, m2);
        float ca = __expf(mx - nm);
        float cb2 = __expf(m2 - nm);
        sum = sum * ca + s2 * cb2;
#pragma unroll
        for (int d = 0; d < 32; d++)
            acc[d] = acc[d] * ca + __shfl_xor_sync(0xffffffffu, acc[d], off) * cb2;
        mx = nm;
    }

    if (active) {
        float inv = 1.0f / sum;
        int b = bh >> 2;
#pragma unroll
        for (int jj = 0; jj < 8; jj++) {
            int c = h * HD + ks * 8 + jj;
            g_ot[((size_t)b * CC + c) * NN + q] = acc[ks * 8 + jj] * inv;
        }
    }
}

// ---------------------------------------------------------------------------
// K3: fused (proj∘convout) GEMM + bilinear x4 upsample, writes d_out.
// grid (16 oc-tiles, B), block 196.
// Phase A: GEMM into ms[32][197-pad].
// Phase B: row-tasks (ch, O): row-interp to tmp[14] regs, then fully-unrolled
//          column loop with compile-time lc/wc -> static indexing, no per-pixel
//          integer math. Lanes map ch=task&31, stride-197 smem: conflict-free.
// ---------------------------------------------------------------------------
#define MS_STRIDE 197

__global__ void outup_kernel(float* __restrict__ out)
{
    __shared__ float wfs[32 * CC];       // 16KB
    __shared__ float bfs[32];
    __shared__ float ms[32 * MS_STRIDE]; // ~24.6KB
    __shared__ int   lo_s[HIN];
    __shared__ float w_s[HIN];

    int b = blockIdx.y;
    int oc0 = blockIdx.x * 32;
    int t = threadIdx.x;

    for (int idx = t; idx < 32 * CC / 4; idx += 196)
        ((float4*)wfs)[idx] = ((const float4*)(g_wf + (size_t)oc0 * CC))[idx];
    if (t < 32) bfs[t] = g_bf[oc0 + t];
    if (t < HIN) {
        float s = (float)(t * 13) / 55.0f;
        int lo = (int)s;
        lo_s[t] = lo;
        w_s[t] = s - (float)lo;
    }
    __syncthreads();

    // Phase A: GEMM (thread = 4 tokens x 8 oc)
    {
        int ng = t % 49, ocg = t / 49;
        int n0 = ng * 4;
        float acc[32];
#pragma unroll
        for (int i = 0; i < 32; i++) acc[i] = 0.0f;

        const float* ob = g_ot + (size_t)b * CC * NN;
        for (int c = 0; c < CC; c++) {
            float4 ov = *(const float4*)(ob + (size_t)c * NN + n0);
#pragma unroll
            for (int k = 0; k < 8; k++) {
                float w = wfs[(ocg * 8 + k) * CC + c];
                acc[k * 4 + 0] += w * ov.x;
                acc[k * 4 + 1] += w * ov.y;
                acc[k * 4 + 2] += w * ov.z;
                acc[k * 4 + 3] += w * ov.w;
            }
        }
#pragma unroll
        for (int k = 0; k < 8; k++) {
            float bv = bfs[ocg * 8 + k];
#pragma unroll
            for (int z = 0; z < 4; z++)
                ms[(ocg * 8 + k) * MS_STRIDE + n0 + z] = acc[k * 4 + z] + bv;
        }
    }
    __syncthreads();

    // Phase B: upsample, one (channel,row) task at a time
    float* obb = out + ((size_t)b * DIMC + oc0) * HIN * HIN;
    for (int task = t; task < 32 * HIN; task += 196) {
        int ch = task & 31;
        int O  = task >> 5;
        const float* src = ms + ch * MS_STRIDE;
        int lr = lo_s[O];
        int hr = min(lr + 1, 13);
        float wr = w_s[O];

        float tmp[14];
#pragma unroll
        for (int j = 0; j < 14; j++) {
            float a = src[lr * WSZ + j];
            float bv = src[hr * WSZ + j];
            tmp[j] = a + wr * (bv - a);
        }

        float4* orow = (float4*)(obb + (size_t)ch * HIN * HIN + O * HIN);
#pragma unroll
        for (int pq = 0; pq < 14; pq++) {
            float4 v;
#pragma unroll
            for (int z = 0; z < 4; z++) {
                const int P  = pq * 4 + z;              // compile-time
                const int lc = (P * 13) / 55;           // compile-time
                const int hc = (lc + 1 < 14) ? lc + 1 : 13;
                const float wc = (float)(P * 13 - lc * 55) * (1.0f / 55.0f);
                float val = tmp[lc] + wc * (tmp[hc] - tmp[lc]);
                ((float*)&v)[z] = val;
            }
            orow[pq] = v;
        }
    }
}

// ---------------------------------------------------------------------------
extern "C" void kernel_launch(void* const* d_in, const int* in_sizes, int n_in,
                              void* d_out, int out_size)
{
    (void)in_sizes; (void)n_in; (void)out_size;
    const float* x        = (const float*)d_in[0];
    const float* conv_w   = (const float*)d_in[1];
    const float* conv_b   = (const float*)d_in[2];
    const float* bn_gamma = (const float*)d_in[3];
    const float* bn_beta  = (const float*)d_in[4];
    const float* bn_mean  = (const float*)d_in[5];
    const float* bn_var   = (const float*)d_in[6];
    const float* qkv_w    = (const float*)d_in[7];
    const float* proj_w   = (const float*)d_in[8];
    const float* proj_b   = (const float*)d_in[9];
    const float* rpb      = (const float*)d_in[10];
    const float* cvo_w    = (const float*)d_in[11];
    const float* cvo_b    = (const float*)d_in[12];
    float* out = (float*)d_out;

    cudaFuncSetAttribute(attn_kernel, cudaFuncAttributeMaxDynamicSharedMemorySize, ATTN_SMEM);

    prep_kernel<<<DIMC + CC, 384>>>(cvo_w, cvo_b, proj_w, proj_b, qkv_w);
    convqkv_kernel<<<dim3(7, BB), 448>>>(x, conv_w, conv_b, bn_gamma, bn_beta, bn_mean, bn_var);
    attn_kernel<<<dim3(4, BB * NHD), 224, ATTN_SMEM>>>(rpb);
    outup_kernel<<<dim3(16, BB), 196>>>(out);
}

// round 10
// speedup vs baseline: 1.3488x; 1.3488x over previous
#include <cuda_runtime.h>

#define BB   32
#define DIMC 512
#define CC   128
#define WSZ  14
#define NN   196
#define NHD  4
#define HD   32
#define HIN  56

// Scratch (device globals; no runtime allocation)
__device__ float g_q[BB * NHD * NN * HD];  // [B][H][N][D] (pre-scaled via wT)
__device__ float g_k[BB * NHD * NN * HD];
__device__ float g_v[BB * NHD * NN * HD];
__device__ float g_ot[BB * CC * NN];       // attention output TRANSPOSED [B][C][N]
__device__ float g_wf[DIMC * CC];          // fused convout@proj weight [512][128]
__device__ float g_bf[DIMC];               // fused bias
__device__ float g_wqkvT[CC * 3 * CC];     // qkv weight transposed [c][j], q rows pre-scaled

// ---------------------------------------------------------------------------
// K0: prep. blocks 0..511: Wf = convout_w @ proj_w, bf = convout_w@proj_b + cb
//          blocks 512..639: transpose qkv_w -> [c][j], q rows pre-scaled
// grid 640, block 384
// ---------------------------------------------------------------------------
__global__ void prep_kernel(const float* __restrict__ cw,
                            const float* __restrict__ cb,
                            const float* __restrict__ pw,
                            const float* __restrict__ pb,
                            const float* __restrict__ qkvw)
{
    int t = threadIdx.x;
    if (blockIdx.x < DIMC) {
        int oc = blockIdx.x;
        __shared__ float row[CC];
        __shared__ float red[CC];
        if (t < CC) row[t] = cw[oc * CC + t];
        __syncthreads();
        if (t < CC) {
            float acc = 0.0f;
            for (int k = 0; k < CC; k++) acc += row[k] * pw[k * CC + t];
            g_wf[oc * CC + t] = acc;
            red[t] = row[t] * pb[t];
        }
        __syncthreads();
        for (int s = 64; s > 0; s >>= 1) {
            if (t < s) red[t] += red[t + s];
            __syncthreads();
        }
        if (t == 0) g_bf[oc] = red[0] + cb[oc];
    } else {
        int c = blockIdx.x - DIMC;      // 0..127
        float v = qkvw[t * CC + c];
        if (t < CC) v *= 0.17677669529663687f;
        g_wqkvT[c * 384 + t] = v;
    }
}

// ---------------------------------------------------------------------------
// K1: FUSED grouped conv 4x4 s4 + BN + ReLU6 + qkv GEMM.
// grid (7 token-tiles, B), block 448.
// ---------------------------------------------------------------------------
#define TS_STRIDE 132

__global__ void __launch_bounds__(448, 2)
convqkv_kernel(const float* __restrict__ x,
               const float* __restrict__ cw,
               const float* __restrict__ cb,
               const float* __restrict__ gamma,
               const float* __restrict__ beta,
               const float* __restrict__ mean,
               const float* __restrict__ var)
{
    __shared__ float ws[CC * 64];          // 32KB conv weights
    __shared__ float bnsc[CC], bnsh[CC];
    __shared__ float ts[28 * TS_STRIDE];   // token tile, padded

    int tile = blockIdx.x, b = blockIdx.y;
    int t = threadIdx.x;

    for (int idx = t; idx < CC * 64 / 4; idx += 448)
        ((float4*)ws)[idx] = ((const float4*)cw)[idx];
    if (t < CC) {
        float sc = gamma[t] * rsqrtf(var[t] + 1e-5f);
        bnsc[t] = sc;
        bnsh[t] = cb[t] * sc + beta[t] - mean[t] * sc;
    }
    __syncthreads();

    // ---- Phase 1: conv ----
    {
        int n = t % 28, cl = t / 28;       // cl 0..15
        int oh = tile * 2 + n / WSZ, ow = n % WSZ;
        const float* xb = x + (size_t)b * DIMC * HIN * HIN + (4 * oh) * HIN + 4 * ow;
#pragma unroll
        for (int p = 0; p < 8; p++) {
            int c = p * 16 + cl;
            float acc = 0.0f;
            const float* wp0 = ws + c * 64;
            const float* xc = xb + (size_t)(4 * c) * HIN * HIN;
#pragma unroll
            for (int i = 0; i < 4; i++) {
                const float* xp = xc + (size_t)i * HIN * HIN;
#pragma unroll
                for (int kh = 0; kh < 4; kh++) {
                    float4 v = *(const float4*)(xp + kh * HIN);
                    const float* wp = wp0 + i * 16 + kh * 4;
                    acc += v.x * wp[0] + v.y * wp[1] + v.z * wp[2] + v.w * wp[3];
                }
            }
            acc = acc * bnsc[c] + bnsh[c];
            ts[n * TS_STRIDE + c] = fminf(fmaxf(acc, 0.0f), 6.0f);
        }
    }
    __syncthreads();

    // ---- Phase 2: qkv GEMM (threads 0..383) ----
    if (t < 384) {
        int jp = (t % 192) * 2;
        int rg = t / 192;
        int n0 = tile * 28;

        float acc0[14], acc1[14];
#pragma unroll
        for (int r = 0; r < 14; r++) { acc0[r] = 0.0f; acc1[r] = 0.0f; }

        const float* tsb = ts + (rg * 14) * TS_STRIDE;
        for (int cq = 0; cq < 32; cq++) {
            int c = cq * 4;
            float2 w0 = *(const float2*)(g_wqkvT + (size_t)(c + 0) * 384 + jp);
            float2 w1 = *(const float2*)(g_wqkvT + (size_t)(c + 1) * 384 + jp);
            float2 w2 = *(const float2*)(g_wqkvT + (size_t)(c + 2) * 384 + jp);
            float2 w3 = *(const float2*)(g_wqkvT + (size_t)(c + 3) * 384 + jp);
#pragma unroll
            for (int r = 0; r < 14; r++) {
                float4 tv = *(const float4*)(tsb + r * TS_STRIDE + c);
                acc0[r] += tv.x * w0.x + tv.y * w1.x + tv.z * w2.x + tv.w * w3.x;
                acc1[r] += tv.x * w0.y + tv.y * w1.y + tv.z * w2.y + tv.w * w3.y;
            }
        }

#pragma unroll
        for (int which = 0; which < 2; which++) {
            int j = jp + which;
            int s = j / CC, rem = j % CC;
            int h = rem / HD, d = rem % HD;
            float* dst = (s == 0) ? g_q : ((s == 1) ? g_k : g_v);
            dst += (((size_t)(b * NHD + h)) * NN + n0 + rg * 14) * HD + d;
            const float* a = which ? acc1 : acc0;
#pragma unroll
            for (int r = 0; r < 14; r++) dst[r * HD] = a[r];
        }
    }
}

// ---------------------------------------------------------------------------
// K2: attention. grid (4 q-tiles, 128 bh), block 224.
// ---------------------------------------------------------------------------
#define KV_STRIDE 36
#define ATTN_SMEM ((196 * KV_STRIDE * 2 + 729) * 4)

__global__ void attn_kernel(const float* __restrict__ rpb)
{
    extern __shared__ float sm[];
    float* ks_s  = sm;
    float* vs_s  = sm + 196 * KV_STRIDE;
    float* rpb_s = sm + 196 * KV_STRIDE * 2;

    int qt = blockIdx.x;
    int bh = blockIdx.y;
    int h  = bh & 3;
    int t  = threadIdx.x;
    int qi = t >> 2, ks = t & 3;
    bool active = (qi < 49);
    int q = active ? (qt * 49 + qi) : 195;

    const float* kb = g_k + (size_t)bh * NN * HD;
    const float* vb = g_v + (size_t)bh * NN * HD;
    for (int idx = t; idx < 196 * 8; idx += 224) {
        int r = idx >> 3, qd = idx & 7;
        *(float4*)(ks_s + r * KV_STRIDE + qd * 4) = ((const float4*)(kb + r * HD))[qd];
        *(float4*)(vs_s + r * KV_STRIDE + qd * 4) = ((const float4*)(vb + r * HD))[qd];
    }
    for (int i = t; i < 729; i += 224) rpb_s[i] = rpb[i * NHD + h];
    __syncthreads();

    float4 q4[8];
    const float4* qp = (const float4*)(g_q + ((size_t)bh * NN + q) * HD);
#pragma unroll
    for (int i = 0; i < 8; i++) q4[i] = qp[i];
    int r1 = q / WSZ, c1 = q % WSZ;

    float mx = -1e30f, sum = 0.0f;
    float acc[32];
#pragma unroll
    for (int d = 0; d < 32; d++) acc[d] = 0.0f;

    int base_m = ks * 49;
    for (int g = 0; g < 7; g++) {
        int m0 = base_m + g * 7;
        float s[7];
#pragma unroll
        for (int u = 0; u < 7; u++) {
            const float* kr = ks_s + (m0 + u) * KV_STRIDE;
            float sv = 0.0f;
#pragma unroll
            for (int qd = 0; qd < 8; qd++) {
                float4 kv = *(const float4*)(kr + qd * 4);
                sv += q4[qd].x * kv.x + q4[qd].y * kv.y + q4[qd].z * kv.z + q4[qd].w * kv.w;
            }
            int m = m0 + u;
            int r2 = m / WSZ, c2 = m % WSZ;
            s[u] = sv + rpb_s[(r1 - r2 + 13) * 27 + (c1 - c2 + 13)];
        }
        float gm = s[0];
#pragma unroll
        for (int u = 1; u < 7; u++) gm = fmaxf(gm, s[u]);
        float nm = fmaxf(mx, gm);
        float corr = __expf(mx - nm);
        mx = nm;
        float ps = 0.0f;
#pragma unroll
        for (int u = 0; u < 7; u++) { s[u] = __expf(s[u] - nm); ps += s[u]; }
        sum = sum * corr + ps;

#pragma unroll
        for (int qd = 0; qd < 8; qd++) {
            float4 vv[7];
#pragma unroll
            for (int u = 0; u < 7; u++)
                vv[u] = *(const float4*)(vs_s + (m0 + u) * KV_STRIDE + qd * 4);
#pragma unroll
            for (int z = 0; z < 4; z++) {
                float a = acc[qd * 4 + z] * corr;
#pragma unroll
                for (int u = 0; u < 7; u++)
                    a += s[u] * ((const float*)&vv[u])[z];
                acc[qd * 4 + z] = a;
            }
        }
    }

#pragma unroll
    for (int off = 1; off <= 2; off <<= 1) {
        float m2 = __shfl_xor_sync(0xffffffffu, mx, off);
        float s2 = __shfl_xor_sync(0xffffffffu, sum, off);
        float nm = fmaxf(mx, m2);
        float ca = __expf(mx - nm);
        float cb2 = __expf(m2 - nm);
        sum = sum * ca + s2 * cb2;
#pragma unroll
        for (int d = 0; d < 32; d++)
            acc[d] = acc[d] * ca + __shfl_xor_sync(0xffffffffu, acc[d], off) * cb2;
        mx = nm;
    }

    if (active) {
        float inv = 1.0f / sum;
        int b = bh >> 2;
#pragma unroll
        for (int jj = 0; jj < 8; jj++) {
            int c = h * HD + ks * 8 + jj;
            g_ot[((size_t)b * CC + c) * NN + q] = acc[ks * 8 + jj] * inv;
        }
    }
}

// ---------------------------------------------------------------------------
// K3: fused (proj∘convout) GEMM + bilinear x4 upsample, writes d_out.
// grid (16 oc-tiles, B), block 196.
// Phase A: GEMM into ms[32][197-pad].
// Phase B: thread = (f = t%14 float4-in-row [FIXED -> col coeffs hoisted],
//          r0 = t/14), iterate rows stride 14. Lanes 0..13 of a warp write
//          14 consecutive float4s -> fully coalesced 224B row segments.
// ---------------------------------------------------------------------------
#define MS_STRIDE 197

__global__ void outup_kernel(float* __restrict__ out)
{
    __shared__ float wfs[32 * CC];       // 16KB
    __shared__ float bfs[32];
    __shared__ float ms[32 * MS_STRIDE]; // ~24.6KB
    __shared__ int   lo_s[HIN];
    __shared__ float w_s[HIN];

    int b = blockIdx.y;
    int oc0 = blockIdx.x * 32;
    int t = threadIdx.x;

    for (int idx = t; idx < 32 * CC / 4; idx += 196)
        ((float4*)wfs)[idx] = ((const float4*)(g_wf + (size_t)oc0 * CC))[idx];
    if (t < 32) bfs[t] = g_bf[oc0 + t];
    if (t < HIN) {
        float s = (float)(t * 13) / 55.0f;
        int lo = (int)s;
        lo_s[t] = lo;
        w_s[t] = s - (float)lo;
    }
    __syncthreads();

    // Phase A: GEMM (thread = 4 tokens x 8 oc)
    {
        int ng = t % 49, ocg = t / 49;
        int n0 = ng * 4;
        float acc[32];
#pragma unroll
        for (int i = 0; i < 32; i++) acc[i] = 0.0f;

        const float* ob = g_ot + (size_t)b * CC * NN;
        for (int c = 0; c < CC; c++) {
            float4 ov = *(const float4*)(ob + (size_t)c * NN + n0);
#pragma unroll
            for (int k = 0; k < 8; k++) {
                float w = wfs[(ocg * 8 + k) * CC + c];
                acc[k * 4 + 0] += w * ov.x;
                acc[k * 4 + 1] += w * ov.y;
                acc[k * 4 + 2] += w * ov.z;
                acc[k * 4 + 3] += w * ov.w;
            }
        }
#pragma unroll
        for (int k = 0; k < 8; k++) {
            float bv = bfs[ocg * 8 + k];
#pragma unroll
            for (int z = 0; z < 4; z++)
                ms[(ocg * 8 + k) * MS_STRIDE + n0 + z] = acc[k * 4 + z] + bv;
        }
    }
    __syncthreads();

    // Phase B: upsample. f fixed per thread -> column coeffs hoisted.
    {
        int f  = t % 14;            // float4 index within output row
        int r0 = t / 14;            // 0..13

        int   lcz[4], hcz[4];
        float wcz[4];
#pragma unroll
        for (int z = 0; z < 4; z++) {
            int P = f * 4 + z;
            int lc = lo_s[P];
            lcz[z] = lc;
            hcz[z] = (lc + 1 < 14) ? lc + 1 : 13;
            wcz[z] = w_s[P];
        }

        float* obb = out + ((size_t)b * DIMC + oc0) * HIN * HIN;
        for (int rb = 0; rb < 128; rb++) {
            int row = r0 + rb * 14;        // 0..1791
            int ch  = row / 56;
            int O   = row - ch * 56;
            int lr = lo_s[O];
            int hr = (lr + 1 < 14) ? lr + 1 : 13;
            float wr = w_s[O];
            const float* src = ms + ch * MS_STRIDE;
            const float* srl = src + lr * WSZ;
            const float* srh = src + hr * WSZ;

            float4 v;
#pragma unroll
            for (int z = 0; z < 4; z++) {
                float al = srl[lcz[z]];
                float ah = srl[hcz[z]];
                float bl = srh[lcz[z]];
                float bh2 = srh[hcz[z]];
                float a  = al + wcz[z] * (ah - al);
                float b2 = bl + wcz[z] * (bh2 - bl);
                ((float*)&v)[z] = a + wr * (b2 - a);
            }
            *(float4*)(obb + (size_t)ch * (HIN * HIN) + O * HIN + f * 4) = v;
        }
    }
}

// ---------------------------------------------------------------------------
extern "C" void kernel_launch(void* const* d_in, const int* in_sizes, int n_in,
                              void* d_out, int out_size)
{
    (void)in_sizes; (void)n_in; (void)out_size;
    const float* x        = (const float*)d_in[0];
    const float* conv_w   = (const float*)d_in[1];
    const float* conv_b   = (const float*)d_in[2];
    const float* bn_gamma = (const float*)d_in[3];
    const float* bn_beta  = (const float*)d_in[4];
    const float* bn_mean  = (const float*)d_in[5];
    const float* bn_var   = (const float*)d_in[6];
    const float* qkv_w    = (const float*)d_in[7];
    const float* proj_w   = (const float*)d_in[8];
    const float* proj_b   = (const float*)d_in[9];
    const float* rpb      = (const float*)d_in[10];
    const float* cvo_w    = (const float*)d_in[11];
    const float* cvo_b    = (const float*)d_in[12];
    float* out = (float*)d_out;

    cudaFuncSetAttribute(attn_kernel, cudaFuncAttributeMaxDynamicSharedMemorySize, ATTN_SMEM);

    prep_kernel<<<DIMC + CC, 384>>>(cvo_w, cvo_b, proj_w, proj_b, qkv_w);
    convqkv_kernel<<<dim3(7, BB), 448>>>(x, conv_w, conv_b, bn_gamma, bn_beta, bn_mean, bn_var);
    attn_kernel<<<dim3(4, BB * NHD), 224, ATTN_SMEM>>>(rpb);
    outup_kernel<<<dim3(16, BB), 196>>>(out);
}